// round 5
// baseline (speedup 1.0000x reference)
#include <cuda_runtime.h>
#include <math.h>
#include <stdint.h>

// Problem constants (fixed by the reference)
#define TOK   8192          // B*S tokens
#define DDIM  1024
#define NEXP  8
#define HDIM  2048
#define RROWS (2*TOK)       // routed rows (top_k = 2)
#define MAXT  144           // >= worst-case sum of ceil(n_e/128) = 135

// ------------------------- device scratch (no cudaMalloc allowed) ----------
static __device__ float g_H[(size_t)RROWS * HDIM];   // FFN1 output (134 MB)
static __device__ float g_Y[(size_t)RROWS * DDIM];   // FFN2 output (67 MB)
static __device__ int   g_eidx[2 * TOK];             // per-token expert ids (2 slots)
static __device__ float g_ew[2 * TOK];               // per-token combine weights
static __device__ int   g_perm[RROWS];               // routed row -> token
static __device__ int   g_tokpos[2 * TOK];           // token slot -> routed row
static __device__ int   g_cnt[NEXP];
static __device__ int   g_off[NEXP + 1];
static __device__ int   g_cur[NEXP];
static __device__ int   g_ntiles;
static __device__ int   g_te[MAXT], g_tr0[MAXT], g_tnr[MAXT];

// ------------------------- small helpers -----------------------------------
__device__ __forceinline__ uint32_t f2tf(float f) {
    uint32_t u;
    asm("cvt.rna.tf32.f32 %0, %1;" : "=r"(u) : "f"(f));
    return u;
}

__device__ __forceinline__ void mma8(float* c, const uint32_t* a, const uint32_t* b) {
    asm volatile(
        "mma.sync.aligned.m16n8k8.row.col.f32.tf32.tf32.f32 "
        "{%0,%1,%2,%3},{%4,%5,%6,%7},{%8,%9},{%0,%1,%2,%3};"
        : "+f"(c[0]), "+f"(c[1]), "+f"(c[2]), "+f"(c[3])
        : "r"(a[0]), "r"(a[1]), "r"(a[2]), "r"(a[3]), "r"(b[0]), "r"(b[1]));
}

__device__ __forceinline__ float gelu_t(float v) {
    // matches jax.nn.gelu(approximate=True)
    float u = 0.7978845608028654f * (v + 0.044715f * v * v * v);
    return 0.5f * v * (1.0f + tanhf(u));
}

// ------------------------- stage kernels ------------------------------------
__global__ void k_init() {
    int i = threadIdx.x;
    if (i < NEXP) g_cnt[i] = 0;
}

// Gating: logits = x @ Wg + bg, softmax top-2 with renormalized weights.
// One warp per token; Wg (32 KB) cached in smem.
__global__ void k_gate(const float* __restrict__ x,
                       const float* __restrict__ Wg,
                       const float* __restrict__ bg) {
    __shared__ float sW[DDIM * NEXP];
    __shared__ float sb[NEXP];
    for (int i = threadIdx.x; i < DDIM * NEXP; i += 256) sW[i] = Wg[i];
    if (threadIdx.x < NEXP) sb[threadIdx.x] = bg[threadIdx.x];
    __syncthreads();

    int w = threadIdx.x >> 5, lane = threadIdx.x & 31;
    int t = blockIdx.x * 8 + w;
    const float* xr = x + (size_t)t * DDIM;

    float acc[NEXP];
#pragma unroll
    for (int e = 0; e < NEXP; e++) acc[e] = 0.0f;
    for (int k = lane; k < DDIM; k += 32) {
        float xv = xr[k];
#pragma unroll
        for (int e = 0; e < NEXP; e++) acc[e] = fmaf(xv, sW[k * NEXP + e], acc[e]);
    }
#pragma unroll
    for (int e = 0; e < NEXP; e++) {
#pragma unroll
        for (int o = 16; o > 0; o >>= 1)
            acc[e] += __shfl_xor_sync(0xffffffffu, acc[e], o);
    }
    if (lane == 0) {
        float l[NEXP];
#pragma unroll
        for (int e = 0; e < NEXP; e++) l[e] = acc[e] + sb[e];
        int i0 = 0;
#pragma unroll
        for (int e = 1; e < NEXP; e++) if (l[e] > l[i0]) i0 = e;
        int i1 = (i0 == 0) ? 1 : 0;
#pragma unroll
        for (int e = 0; e < NEXP; e++) if (e != i0 && l[e] > l[i1]) i1 = e;
        // renormalized top-2 softmax weight = sigmoid(l0 - l1)
        float w0 = 1.0f / (1.0f + expf(l[i1] - l[i0]));
        g_eidx[2 * t]     = i0;
        g_eidx[2 * t + 1] = i1;
        g_ew[2 * t]       = w0;
        g_ew[2 * t + 1]   = 1.0f - w0;
        atomicAdd(&g_cnt[i0], 1);
        atomicAdd(&g_cnt[i1], 1);
    }
}

// Offsets + tile table (tiny serial work, one thread)
__global__ void k_offsets() {
    if (threadIdx.x == 0) {
        int off = 0, nt = 0;
        for (int e = 0; e < NEXP; e++) {
            g_off[e] = off;
            g_cur[e] = 0;
            int c = g_cnt[e];
            int tiles = (c + 127) >> 7;
            for (int m = 0; m < tiles; m++) {
                g_te[nt]  = e;
                g_tr0[nt] = off + m * 128;
                int nr = c - m * 128;
                if (nr > 128) nr = 128;
                g_tnr[nt] = nr;
                nt++;
            }
            off += c;
        }
        g_off[NEXP] = off;
        g_ntiles = nt;
    }
}

__global__ void k_scatter() {
    int t = blockIdx.x * blockDim.x + threadIdx.x;
    if (t >= TOK) return;
#pragma unroll
    for (int k = 0; k < 2; k++) {
        int e = g_eidx[2 * t + k];
        int p = g_off[e] + atomicAdd(&g_cur[e], 1);
        g_perm[p] = t;
        g_tokpos[2 * t + k] = p;
    }
}

// -------- grouped GEMM: C[tile] = act(A @ B[e] + bias[e]) -------------------
// 128x128 block tile, BK=16, 256 threads, warp tile 64x32, m16n8k8 tf32.
// GATHER: A rows indirected through g_perm (GEMM1). Otherwise A = g_H (GEMM2).
// GELU:   gelu epilogue, C = g_H (GEMM1). Otherwise C = g_Y (GEMM2).
template <int KDIM, int LDB, int LDC, bool GATHER, bool GELU>
__global__ __launch_bounds__(256, 1) void k_gemm(const float* __restrict__ Aglob,
                                                 const float* __restrict__ Bglob,
                                                 const float* __restrict__ biasg) {
    int jt = blockIdx.y;
    if (jt >= g_ntiles) return;
    int e = g_te[jt], row0 = g_tr0[jt], nrows = g_tnr[jt];
    int n0 = blockIdx.x * 128;

    const float* Bp = Bglob + (size_t)e * KDIM * LDB;
    const float* bp = biasg + (size_t)e * LDB;

    // Bank-mapping: A frag load addr = m*20+k -> (20*grp + tig) tiles 32 banks.
    //               B frag load addr = k*136+n -> (8*tig + grp) tiles 32 banks.
    __shared__ __align__(16) uint32_t As[2][128][20];
    __shared__ __align__(16) uint32_t Bs[2][16][136];

    int tid  = threadIdx.x;
    int lane = tid & 31, warp = tid >> 5;
    int wm = warp & 1, wn = warp >> 1;     // warp grid 2(M) x 4(N)
    int grp = lane >> 2, tig = lane & 3;

    // global->smem load assignment
    int ar0 = tid >> 2, ar1 = ar0 + 64;    // A rows (2 per thread)
    int ak  = (tid & 3) << 2;              // A k offset (float4)
    int bk0 = tid >> 5, bk1 = bk0 + 8;     // B k rows (2 per thread)
    int bn  = (tid & 31) << 2;             // B n offset (float4)

    int gr0 = row0 + ar0; if (gr0 > RROWS - 1) gr0 = RROWS - 1;
    int gr1 = row0 + ar1; if (gr1 > RROWS - 1) gr1 = RROWS - 1;

    const float *Ab0, *Ab1;
    if (GATHER) {
        Ab0 = Aglob + (size_t)g_perm[gr0] * KDIM;
        Ab1 = Aglob + (size_t)g_perm[gr1] * KDIM;
    } else {
        Ab0 = g_H + (size_t)gr0 * KDIM;
        Ab1 = g_H + (size_t)gr1 * KDIM;
    }
    const float* pA0 = Ab0 + ak;
    const float* pA1 = Ab1 + ak;
    const float* pB0 = Bp + (size_t)bk0 * LDB + n0 + bn;
    const float* pB1 = Bp + (size_t)bk1 * LDB + n0 + bn;

    float acc[4][4][4];
#pragma unroll
    for (int mi = 0; mi < 4; mi++)
#pragma unroll
        for (int ni = 0; ni < 4; ni++)
#pragma unroll
            for (int q = 0; q < 4; q++) acc[mi][ni][q] = 0.0f;

    float4 ra0, ra1, rb0, rb1;

    auto sts = [&](int b) {
        uint4 u;
        u.x = f2tf(ra0.x); u.y = f2tf(ra0.y); u.z = f2tf(ra0.z); u.w = f2tf(ra0.w);
        *(uint4*)&As[b][ar0][ak] = u;
        u.x = f2tf(ra1.x); u.y = f2tf(ra1.y); u.z = f2tf(ra1.z); u.w = f2tf(ra1.w);
        *(uint4*)&As[b][ar1][ak] = u;
        u.x = f2tf(rb0.x); u.y = f2tf(rb0.y); u.z = f2tf(rb0.z); u.w = f2tf(rb0.w);
        *(uint4*)&Bs[b][bk0][bn] = u;
        u.x = f2tf(rb1.x); u.y = f2tf(rb1.y); u.z = f2tf(rb1.z); u.w = f2tf(rb1.w);
        *(uint4*)&Bs[b][bk1][bn] = u;
    };

    // prologue: stage k-block 0
    ra0 = *(const float4*)pA0;  ra1 = *(const float4*)pA1;
    rb0 = *(const float4*)pB0;  rb1 = *(const float4*)pB1;
    pA0 += 16; pA1 += 16;
    pB0 += (size_t)16 * LDB; pB1 += (size_t)16 * LDB;
    sts(0);
    __syncthreads();

    const int NIT = KDIM / 16;
    int buf = 0;
    for (int kt = 0; kt < NIT; kt++) {
        if (kt + 1 < NIT) {
            ra0 = *(const float4*)pA0;  ra1 = *(const float4*)pA1;
            rb0 = *(const float4*)pB0;  rb1 = *(const float4*)pB1;
            pA0 += 16; pA1 += 16;
            pB0 += (size_t)16 * LDB; pB1 += (size_t)16 * LDB;
        }
#pragma unroll
        for (int kk = 0; kk < 2; kk++) {
            int kb = kk * 8;
            uint32_t af[4][4];
            uint32_t bf[4][2];
#pragma unroll
            for (int mi = 0; mi < 4; mi++) {
                int m = wm * 64 + mi * 16 + grp;
                af[mi][0] = As[buf][m][kb + tig];
                af[mi][1] = As[buf][m + 8][kb + tig];
                af[mi][2] = As[buf][m][kb + tig + 4];
                af[mi][3] = As[buf][m + 8][kb + tig + 4];
            }
#pragma unroll
            for (int ni = 0; ni < 4; ni++) {
                int n = wn * 32 + ni * 8 + grp;
                bf[ni][0] = Bs[buf][kb + tig][n];
                bf[ni][1] = Bs[buf][kb + tig + 4][n];
            }
#pragma unroll
            for (int mi = 0; mi < 4; mi++)
#pragma unroll
                for (int ni = 0; ni < 4; ni++)
                    mma8(acc[mi][ni], af[mi], bf[ni]);
        }
        if (kt + 1 < NIT) sts(buf ^ 1);
        __syncthreads();
        buf ^= 1;
    }

    // epilogue
    float* Cp = GELU ? g_H : g_Y;
#pragma unroll
    for (int mi = 0; mi < 4; mi++) {
        int r = wm * 64 + mi * 16 + grp;
#pragma unroll
        for (int ni = 0; ni < 4; ni++) {
            int nc = n0 + wn * 32 + ni * 8 + 2 * tig;
            float bb0 = bp[nc], bb1 = bp[nc + 1];
            float v0 = acc[mi][ni][0] + bb0, v1 = acc[mi][ni][1] + bb1;
            float v2 = acc[mi][ni][2] + bb0, v3 = acc[mi][ni][3] + bb1;
            if (GELU) {
                v0 = gelu_t(v0); v1 = gelu_t(v1);
                v2 = gelu_t(v2); v3 = gelu_t(v3);
            }
            if (r < nrows) {
                float2 s = make_float2(v0, v1);
                *(float2*)&Cp[(size_t)(row0 + r) * LDC + nc] = s;
            }
            if (r + 8 < nrows) {
                float2 s = make_float2(v2, v3);
                *(float2*)&Cp[(size_t)(row0 + r + 8) * LDC + nc] = s;
            }
        }
    }
}

// out[t] = w0 * Y[pos0(t)] + w1 * Y[pos1(t)]
__global__ void k_combine(float* __restrict__ out) {
    int idx = blockIdx.x * 256 + threadIdx.x;    // over TOK * DDIM / 4
    int t  = idx >> 8;                           // DDIM/4 = 256
    int dq = idx & 255;
    int p0 = g_tokpos[2 * t], p1 = g_tokpos[2 * t + 1];
    float w0 = g_ew[2 * t], w1 = g_ew[2 * t + 1];
    const float4* Y = (const float4*)g_Y;
    float4 a = Y[(size_t)p0 * 256 + dq];
    float4 b = Y[(size_t)p1 * 256 + dq];
    float4 r;
    r.x = w0 * a.x + w1 * b.x;
    r.y = w0 * a.y + w1 * b.y;
    r.z = w0 * a.z + w1 * b.z;
    r.w = w0 * a.w + w1 * b.w;
    ((float4*)out)[idx] = r;
}

// ------------------------- launch ------------------------------------------
extern "C" void kernel_launch(void* const* d_in, const int* in_sizes, int n_in,
                              void* d_out, int out_size) {
    // metadata order: x, top_k(scalar, maybe absent), Wg, bg, W1, b1, W2, b2
    int base = (n_in >= 8) ? 1 : 0;
    const float* x  = (const float*)d_in[0];
    const float* Wg = (const float*)d_in[base + 1];
    const float* bg = (const float*)d_in[base + 2];
    const float* W1 = (const float*)d_in[base + 3];
    const float* b1 = (const float*)d_in[base + 4];
    const float* W2 = (const float*)d_in[base + 5];
    const float* b2 = (const float*)d_in[base + 6];
    float* out = (float*)d_out;
    (void)in_sizes; (void)out_size;

    k_init<<<1, 32>>>();
    k_gate<<<TOK / 8, 256>>>(x, Wg, bg);
    k_offsets<<<1, 32>>>();
    k_scatter<<<(TOK + 255) / 256, 256>>>();
    // FFN1: [R rows] x [D -> H] gathered from x, gelu, into g_H
    k_gemm<DDIM, HDIM, HDIM, true,  true ><<<dim3(HDIM / 128, MAXT), 256>>>(x, W1, b1);
    // FFN2: [R rows] x [H -> D] from g_H, into g_Y
    k_gemm<HDIM, DDIM, DDIM, false, false><<<dim3(DDIM / 128, MAXT), 256>>>(x, W2, b2);
    k_combine<<<(TOK * DDIM / 4) / 256, 256>>>(out);
}